// round 8
// baseline (speedup 1.0000x reference)
#include <cuda_runtime.h>
#include <cstdint>

#define NB 128
#define NPTS 16384
#define GH 128
#define GW 128
#define NV (GH*GW)
#define NPART_OUT 512
#define NTHR 512
#define EPT (NV/NTHR)   // 32 elements per thread

// Reference execution model (eager JAX + compiled lax.scan):
//   coords:      c(i) = rn(-0.3 + rn(i*vsz))          (eager ops, no fma)
//   init dist²:  rn(rn(dx*dx) + rn(dy*dy))            (eager, form0)
//   scan dist²:  fma(dx, dx, rn(dy*dy))               (fused scan body, form2)
//   d = sqrt.rn(d²); argmax in sqrt domain, first-index tie-break.

// Scratch occupancy flags (device global: allocation-free)
__device__ unsigned char g_occ[NB * NV];

__global__ void k_zero() {
    int i = blockIdx.x * blockDim.x + threadIdx.x;
    reinterpret_cast<uint4*>(g_occ)[i] = make_uint4(0u, 0u, 0u, 0u);
}

// ---------------------------------------------------------------------------
// Kernel 1: particle -> occupancy scatter (round-half-even, clip, set-1)
// ---------------------------------------------------------------------------
__global__ void k_scatter(const float* __restrict__ s) {
    int t = blockIdx.x * blockDim.x + threadIdx.x;
    if (t >= NB * NPTS) return;
    float x = s[3 * t + 0];
    float y = s[3 * t + 1];
    float nx = __fmul_rn(__fdiv_rn(__fsub_rn(x, -0.3f), 0.6f), 127.0f);
    float ny = __fmul_rn(__fdiv_rn(__fsub_rn(y, -0.3f), 0.6f), 127.0f);
    int ix = (int)rintf(nx);  ix = min(max(ix, 0), GH - 1);
    int iy = (int)rintf(ny);  iy = min(max(iy, 0), GW - 1);
    int b = t >> 14;   // t / NPTS
    g_occ[b * NV + (ix << 7) + iy] = 1;
}

// voxel coordinate: eager (plain) form
__device__ __forceinline__ float coordf(int a, float vsz) {
    return __fadd_rn(-0.3f, __fmul_rn((float)a, vsz));
}

// ---------------------------------------------------------------------------
// Kernel 2: mask + farthest point sampling. One CTA per batch.
// d^2 state in 32 registers/thread; colX = raw dx per row, colY = rn(dy^2)
// per col, so both form0 (init) and form2 (scan) derive from shared columns.
// ---------------------------------------------------------------------------
__global__ void __launch_bounds__(NTHR, 1) k_fps(
    const float* __restrict__ action,
    const float* __restrict__ cam,
    const float* __restrict__ wv,
    float* __restrict__ out)
{
    __shared__ float colX[GH];   // raw dx per row i
    __shared__ float colY[GW];   // rn(dy*dy) per col j
    __shared__ unsigned long long red[NTHR / 32];
    __shared__ int   s_fp;
    __shared__ float s_bias;
    __shared__ int   s_first;

    const int tid = threadIdx.x;
    const int b   = blockIdx.x;
    const float vsz = __fdiv_rn(0.6f, 127.0f);
    const float NEG_INF = __int_as_float(0xFF800000);
    const float POS_INF = __int_as_float(0x7F800000);

    // ---- per-batch bias: M = T_gl @ E (= inv(inv(E)@T_gl)); sign margin ~2 --
    if (tid == 0) {
        const float tg[3] = {1.0f, -1.0f, -1.0f};
        float a0 = action[b * 4 + 0], a1 = action[b * 4 + 1];
        float a2 = action[b * 4 + 2], a3 = action[b * 4 + 3];
        float bias = 0.0f;
        #pragma unroll
        for (int r = 0; r < 3; r++) {
            float m0 = tg[r] * cam[r * 4 + 0];
            float m2 = tg[r] * cam[r * 4 + 2];
            float m3 = tg[r] * cam[r * 4 + 3];
            float s3 = (m0 * a0 + m2 * (-a1) + m3) / 24.0f;
            float e3 = (m0 * a2 + m2 * (-a3) + m3) / 24.0f;
            bias += wv[r] * s3 + wv[3 + r] * e3;
        }
        s_bias  = bias;
        s_first = 0x7FFFFFFF;
    }
    __syncthreads();
    const float bias = s_bias;
    const bool mOcc = (__fadd_rn(2.0f, bias) >= 0.0f);
    const bool mEmp = (__fsub_rn(bias, 2.0f) >= 0.0f);

    // ---- init mask / d^2 state; find first masked voxel ----
    float dsq[EPT];
    int firstM = 0x7FFFFFFF;
    #pragma unroll
    for (int k = 0; k < EPT; k++) {
        int v = tid + k * NTHR;
        bool m = g_occ[b * NV + v] ? mOcc : mEmp;
        dsq[k] = m ? POS_INF : NEG_INF;
        if (m && firstM == 0x7FFFFFFF) firstM = v;
    }
    if (firstM != 0x7FFFFFFF) atomicMin(&s_first, firstM);
    __syncthreads();
    int startv = s_first;
    if (startv == 0x7FFFFFFF) {
        startv = 0;
        #pragma unroll
        for (int k = 0; k < EPT; k++) dsq[k] = POS_INF;
    }
    if (tid == 0) {
        size_t o3 = (size_t)b * NPART_OUT * 3;
        out[o3 + 0] = coordf(startv >> 7, vsz);
        out[o3 + 1] = coordf(startv & 127, vsz);
        out[o3 + 2] = 0.745f;
    }

    int fpv = startv;
    const int i0 = tid >> 7;
    const int jj = tid & 127;

    for (int it = 1; it < NPART_OUT; it++) {
        const int pi = fpv >> 7, pj = fpv & 127;
        const bool firstIter = (it == 1);   // eager init distances: form0
        __syncthreads();
        if (tid < GH) {
            colX[tid] = __fsub_rn(coordf(tid, vsz), coordf(pi, vsz));  // raw dx
        } else if (tid < GH + GW) {
            int j = tid - GH;
            float d = __fsub_rn(coordf(j, vsz), coordf(pj, vsz));
            colY[j] = __fmul_rn(d, d);                                  // rn(dy^2)
        }
        __syncthreads();

        const float cy = colY[jj];         // per-thread constant this iteration
        float best = NEG_INF;
        int   bidx = 0;
        #pragma unroll
        for (int k = 0; k < EPT; k++) {
            const float cx = colX[i0 + 4 * k];
            float sv;
            if (firstIter)
                sv = __fadd_rn(__fmul_rn(cx, cx), cy);   // form0: rn(dx^2)+rn(dy^2)
            else
                sv = __fmaf_rn(cx, cx, cy);              // form2: fma(dx,dx,rn(dy^2))
            float dv = fminf(dsq[k], sv);
            dsq[k] = dv;
            float key = (dv >= 0.0f) ? __fsqrt_rn(dv) : NEG_INF;
            if (key > best) { best = key; bidx = tid + k * NTHR; }
        }

        unsigned ub = __float_as_uint(best);
        ub = (ub & 0x80000000u) ? ~ub : (ub | 0x80000000u);
        unsigned long long pk =
            ((unsigned long long)ub << 32) | (unsigned)(~bidx);
        #pragma unroll
        for (int o = 16; o > 0; o >>= 1) {
            unsigned long long other = __shfl_down_sync(0xFFFFFFFFu, pk, o);
            if (other > pk) pk = other;
        }
        if ((tid & 31) == 0) red[tid >> 5] = pk;
        __syncthreads();
        if (tid < 32) {
            unsigned long long p2 = (tid < NTHR / 32) ? red[tid] : 0ull;
            #pragma unroll
            for (int o = 8; o > 0; o >>= 1) {
                unsigned long long other = __shfl_down_sync(0xFFFFFFFFu, p2, o);
                if (other > p2) p2 = other;
            }
            if (tid == 0) {
                int vb = ~((int)(unsigned)(p2 & 0xFFFFFFFFull));
                s_fp = vb;
                size_t o3 = ((size_t)b * NPART_OUT + it) * 3;
                out[o3 + 0] = coordf(vb >> 7, vsz);
                out[o3 + 1] = coordf(vb & 127, vsz);
                out[o3 + 2] = 0.745f;
            }
        }
        __syncthreads();
        fpv = s_fp;
    }
}

// ---------------------------------------------------------------------------
// Inputs bound BY ELEMENT COUNT (all five sizes distinct):
//   s_cur 6291456 | action 512 | cam 16 | w_action 6 | n_particles 1 (unused)
// Output: f32 (128, 512, 3)
// ---------------------------------------------------------------------------
extern "C" void kernel_launch(void* const* d_in, const int* in_sizes, int n_in,
                              void* d_out, int out_size) {
    const float* s_cur  = nullptr;
    const float* action = nullptr;
    const float* cam    = nullptr;
    const float* wv     = nullptr;
    for (int i = 0; i < n_in; i++) {
        switch (in_sizes[i]) {
            case NB * NPTS * 3: s_cur  = (const float*)d_in[i]; break;
            case NB * 4:        action = (const float*)d_in[i]; break;
            case 16:            cam    = (const float*)d_in[i]; break;
            case 6:             wv     = (const float*)d_in[i]; break;
            default: break;
        }
    }
    if (!s_cur)  s_cur  = (const float*)d_in[0];
    if (!action) action = (const float*)d_in[1];
    if (!cam)    cam    = (const float*)d_in[2];
    if (!wv)     wv     = (const float*)d_in[3];
    float* out = (float*)d_out;

    k_zero<<<(NB * NV / 16) / 256, 256>>>();
    k_scatter<<<(NB * NPTS) / 256, 256>>>(s_cur);
    k_fps<<<NB, NTHR>>>(action, cam, wv, out);
}

// round 9
// speedup vs baseline: 3.7082x; 3.7082x over previous
#include <cuda_runtime.h>
#include <cstdint>

#define NB 128
#define NPTS 16384
#define GH 128
#define GW 128
#define NV (GH*GW)
#define NPART_OUT 512
#define NTHR 512
#define EPT (NV/NTHR)   // 32 elements per thread
#define NWARP (NTHR/32)

// Reference execution model (eager JAX + compiled lax.scan) — bitwise:
//   coords:      c(i) = rn(-0.3 + rn(i*vsz))          (eager, no fma)
//   init dist²:  rn(rn(dx*dx) + rn(dy*dy))            (eager, form0)
//   scan dist²:  fma(dx, dx, rn(dy*dy))               (fused scan body, form2)
//   d = sqrt.rn(d²); argmax in sqrt domain, first-index tie-break.
// Sqrt-free argmax: preimage of S=sqrt_rn(M2) under monotone sqrt_rn is an
// interval [L, M2]; first index with d² >= L == reference argmax. Exact.

__device__ unsigned char g_occ[NB * NV];

__global__ void k_zero() {
    int i = blockIdx.x * blockDim.x + threadIdx.x;
    reinterpret_cast<uint4*>(g_occ)[i] = make_uint4(0u, 0u, 0u, 0u);
}

__global__ void k_scatter(const float* __restrict__ s) {
    int t = blockIdx.x * blockDim.x + threadIdx.x;
    if (t >= NB * NPTS) return;
    float x = s[3 * t + 0];
    float y = s[3 * t + 1];
    float nx = __fmul_rn(__fdiv_rn(__fsub_rn(x, -0.3f), 0.6f), 127.0f);
    float ny = __fmul_rn(__fdiv_rn(__fsub_rn(y, -0.3f), 0.6f), 127.0f);
    int ix = (int)rintf(nx);  ix = min(max(ix, 0), GH - 1);
    int iy = (int)rintf(ny);  iy = min(max(iy, 0), GW - 1);
    int b = t >> 14;
    g_occ[b * NV + (ix << 7) + iy] = 1;
}

__device__ __forceinline__ float coordf(int a, float vsz) {
    return __fadd_rn(-0.3f, __fmul_rn((float)a, vsz));
}

__global__ void __launch_bounds__(NTHR, 1) k_fps(
    const float* __restrict__ action,
    const float* __restrict__ cam,
    const float* __restrict__ wv,
    float* __restrict__ out)
{
    __shared__ float colX[GH];     // raw dx per row i
    __shared__ float colY[GW];     // rn(dy*dy) per col j
    __shared__ float redf[NWARP];  // per-warp max d²
    __shared__ int   redi[NWARP];  // per-warp min index in tie window
    __shared__ float s_bias;
    __shared__ int   s_first;

    const int tid  = threadIdx.x;
    const int lane = tid & 31;
    const int wid  = tid >> 5;
    const int b    = blockIdx.x;
    const float vsz = __fdiv_rn(0.6f, 127.0f);
    const float NEG_INF = __int_as_float(0xFF800000);
    const float POS_INF = __int_as_float(0x7F800000);
    const int   BIGIDX  = 0x7FFFFFFF;

    // ---- per-batch bias: M = T_gl @ E; only its sign margin matters --------
    if (tid == 0) {
        const float tg[3] = {1.0f, -1.0f, -1.0f};
        float a0 = action[b * 4 + 0], a1 = action[b * 4 + 1];
        float a2 = action[b * 4 + 2], a3 = action[b * 4 + 3];
        float bias = 0.0f;
        #pragma unroll
        for (int r = 0; r < 3; r++) {
            float m0 = tg[r] * cam[r * 4 + 0];
            float m2 = tg[r] * cam[r * 4 + 2];
            float m3 = tg[r] * cam[r * 4 + 3];
            float s3 = (m0 * a0 + m2 * (-a1) + m3) / 24.0f;
            float e3 = (m0 * a2 + m2 * (-a3) + m3) / 24.0f;
            bias += wv[r] * s3 + wv[3 + r] * e3;
        }
        s_bias  = bias;
        s_first = BIGIDX;
    }
    __syncthreads();
    const float bias = s_bias;
    const bool mOcc = (__fadd_rn(2.0f, bias) >= 0.0f);
    const bool mEmp = (__fsub_rn(bias, 2.0f) >= 0.0f);

    // ---- init mask / d² state; first masked voxel --------------------------
    float dsq[EPT];
    int firstM = BIGIDX;
    #pragma unroll
    for (int k = 0; k < EPT; k++) {
        int v = tid + k * NTHR;
        bool m = g_occ[b * NV + v] ? mOcc : mEmp;
        dsq[k] = m ? POS_INF : NEG_INF;
        if (m && firstM == BIGIDX) firstM = v;
    }
    if (firstM != BIGIDX) atomicMin(&s_first, firstM);
    __syncthreads();
    int startv = s_first;
    if (startv == BIGIDX) {
        startv = 0;
        #pragma unroll
        for (int k = 0; k < EPT; k++) dsq[k] = POS_INF;
    }
    if (tid == 0) {
        size_t o3 = (size_t)b * NPART_OUT * 3;
        out[o3 + 0] = coordf(startv >> 7, vsz);
        out[o3 + 1] = coordf(startv & 127, vsz);
        out[o3 + 2] = 0.745f;
    }

    int fpv = startv;
    const int i0 = tid >> 7;     // warp-uniform row base
    const int jj = tid & 127;

    for (int it = 1; it < NPART_OUT; it++) {
        const int pi = fpv >> 7, pj = fpv & 127;
        // ---- build distance columns (cols not read until after syncB) ------
        if (tid < GH) {
            colX[tid] = __fsub_rn(coordf(tid, vsz), coordf(pi, vsz));
        } else if (tid < GH + GW) {
            int j = tid - GH;
            float d = __fsub_rn(coordf(j, vsz), coordf(pj, vsz));
            colY[j] = __fmul_rn(d, d);
        }
        __syncthreads();                                   // syncB

        // ---- pass 1: min-update + block max of d² (4 parallel chains) ------
        const float cy = colY[jj];
        float m0 = NEG_INF, m1 = NEG_INF, m2a = NEG_INF, m3 = NEG_INF;
        if (it == 1) {
            #pragma unroll
            for (int k = 0; k < EPT; k += 4) {
                float s0 = __fadd_rn(__fmul_rn(colX[i0 + 4*(k+0)], colX[i0 + 4*(k+0)]), cy);
                float s1 = __fadd_rn(__fmul_rn(colX[i0 + 4*(k+1)], colX[i0 + 4*(k+1)]), cy);
                float s2 = __fadd_rn(__fmul_rn(colX[i0 + 4*(k+2)], colX[i0 + 4*(k+2)]), cy);
                float s3 = __fadd_rn(__fmul_rn(colX[i0 + 4*(k+3)], colX[i0 + 4*(k+3)]), cy);
                dsq[k+0] = fminf(dsq[k+0], s0);  m0 = fmaxf(m0, dsq[k+0]);
                dsq[k+1] = fminf(dsq[k+1], s1);  m1 = fmaxf(m1, dsq[k+1]);
                dsq[k+2] = fminf(dsq[k+2], s2);  m2a = fmaxf(m2a, dsq[k+2]);
                dsq[k+3] = fminf(dsq[k+3], s3);  m3 = fmaxf(m3, dsq[k+3]);
            }
        } else {
            #pragma unroll
            for (int k = 0; k < EPT; k += 4) {
                float c0 = colX[i0 + 4*(k+0)], c1 = colX[i0 + 4*(k+1)];
                float c2 = colX[i0 + 4*(k+2)], c3 = colX[i0 + 4*(k+3)];
                float s0 = __fmaf_rn(c0, c0, cy);
                float s1 = __fmaf_rn(c1, c1, cy);
                float s2 = __fmaf_rn(c2, c2, cy);
                float s3 = __fmaf_rn(c3, c3, cy);
                dsq[k+0] = fminf(dsq[k+0], s0);  m0 = fmaxf(m0, dsq[k+0]);
                dsq[k+1] = fminf(dsq[k+1], s1);  m1 = fmaxf(m1, dsq[k+1]);
                dsq[k+2] = fminf(dsq[k+2], s2);  m2a = fmaxf(m2a, dsq[k+2]);
                dsq[k+3] = fminf(dsq[k+3], s3);  m3 = fmaxf(m3, dsq[k+3]);
            }
        }
        float wmax = fmaxf(fmaxf(m0, m1), fmaxf(m2a, m3));
        #pragma unroll
        for (int o = 16; o > 0; o >>= 1)
            wmax = fmaxf(wmax, __shfl_xor_sync(0xFFFFFFFFu, wmax, o));
        if (lane == 0) redf[wid] = wmax;
        __syncthreads();                                   // syncC

        // ---- every thread: block max M2, then tie-window lower bound L -----
        float M2 = redf[0];
        #pragma unroll
        for (int w = 1; w < NWARP; w++) M2 = fmaxf(M2, redf[w]);
        float L = M2;
        if (M2 > 0.0f) {
            float S = __fsqrt_rn(M2);
            unsigned u = __float_as_uint(M2);
            #pragma unroll 1
            while (u > 0u && __fsqrt_rn(__uint_as_float(u - 1u)) == S) u--;
            L = __uint_as_float(u);
        }

        // ---- pass 2: first index with d² >= L (4 parallel min chains) ------
        int b0 = BIGIDX, b1 = BIGIDX, b2 = BIGIDX, b3 = BIGIDX;
        #pragma unroll
        for (int k = 0; k < EPT; k += 4) {
            b0 = min(b0, (dsq[k+0] >= L) ? (tid + (k+0) * NTHR) : BIGIDX);
            b1 = min(b1, (dsq[k+1] >= L) ? (tid + (k+1) * NTHR) : BIGIDX);
            b2 = min(b2, (dsq[k+2] >= L) ? (tid + (k+2) * NTHR) : BIGIDX);
            b3 = min(b3, (dsq[k+3] >= L) ? (tid + (k+3) * NTHR) : BIGIDX);
        }
        int wmin = min(min(b0, b1), min(b2, b3));
        #pragma unroll
        for (int o = 16; o > 0; o >>= 1)
            wmin = min(wmin, __shfl_xor_sync(0xFFFFFFFFu, wmin, o));
        if (lane == 0) redi[wid] = wmin;
        __syncthreads();                                   // syncE

        int v = redi[0];
        #pragma unroll
        for (int w = 1; w < NWARP; w++) v = min(v, redi[w]);
        fpv = v;
        if (tid == 0) {
            size_t o3 = ((size_t)b * NPART_OUT + it) * 3;
            out[o3 + 0] = coordf(v >> 7, vsz);
            out[o3 + 1] = coordf(v & 127, vsz);
            out[o3 + 2] = 0.745f;
        }
        // col rewrite next iteration is ordered after this syncE: pass-1 col
        // reads ended before syncC < syncE. Safe with 3 barriers/iteration.
    }
}

// ---------------------------------------------------------------------------
// Inputs bound BY ELEMENT COUNT (all five sizes distinct):
//   s_cur 6291456 | action 512 | cam 16 | w_action 6 | n_particles 1 (unused)
// Output: f32 (128, 512, 3)
// ---------------------------------------------------------------------------
extern "C" void kernel_launch(void* const* d_in, const int* in_sizes, int n_in,
                              void* d_out, int out_size) {
    const float* s_cur  = nullptr;
    const float* action = nullptr;
    const float* cam    = nullptr;
    const float* wv     = nullptr;
    for (int i = 0; i < n_in; i++) {
        switch (in_sizes[i]) {
            case NB * NPTS * 3: s_cur  = (const float*)d_in[i]; break;
            case NB * 4:        action = (const float*)d_in[i]; break;
            case 16:            cam    = (const float*)d_in[i]; break;
            case 6:             wv     = (const float*)d_in[i]; break;
            default: break;
        }
    }
    if (!s_cur)  s_cur  = (const float*)d_in[0];
    if (!action) action = (const float*)d_in[1];
    if (!cam)    cam    = (const float*)d_in[2];
    if (!wv)     wv     = (const float*)d_in[3];
    float* out = (float*)d_out;

    k_zero<<<(NB * NV / 16) / 256, 256>>>();
    k_scatter<<<(NB * NPTS) / 256, 256>>>(s_cur);
    k_fps<<<NB, NTHR>>>(action, cam, wv, out);
}

// round 10
// speedup vs baseline: 4.1232x; 1.1119x over previous
#include <cuda_runtime.h>
#include <cstdint>

#define NB 128
#define NPTS 16384
#define GH 128
#define GW 128
#define NV (GH*GW)
#define NPART_OUT 512
#define NTHR 512
#define EPT (NV/NTHR)   // 32 elements per thread
#define NWARP (NTHR/32)

// Reference execution model (eager JAX + compiled lax.scan) — bitwise:
//   coords:      c(i) = rn(-0.3 + rn(i*vsz))          (eager, no fma)
//   init dist²:  rn(rn(dx*dx) + rn(dy*dy))            (eager, form0)
//   scan dist²:  fma(dx, dx, rn(dy*dy))               (fused scan body, form2)
//   d = sqrt.rn(d²); argmax in sqrt domain, first-index tie-break.
// Sqrt-free argmax: preimage of S=sqrt_rn(M2) under monotone sqrt_rn is an
// interval [L, M2]; first index with d² >= L == reference argmax. Exact.
// FFMA2 (fma.rn.f32x2) is IEEE rn per lane == scalar FFMA bitwise.

__device__ unsigned char g_occ[NB * NV];

__global__ void k_zero() {
    int i = blockIdx.x * blockDim.x + threadIdx.x;
    reinterpret_cast<uint4*>(g_occ)[i] = make_uint4(0u, 0u, 0u, 0u);
}

__global__ void k_scatter(const float* __restrict__ s) {
    int t = blockIdx.x * blockDim.x + threadIdx.x;
    if (t >= NB * NPTS) return;
    float x = s[3 * t + 0];
    float y = s[3 * t + 1];
    float nx = __fmul_rn(__fdiv_rn(__fsub_rn(x, -0.3f), 0.6f), 127.0f);
    float ny = __fmul_rn(__fdiv_rn(__fsub_rn(y, -0.3f), 0.6f), 127.0f);
    int ix = (int)rintf(nx);  ix = min(max(ix, 0), GH - 1);
    int iy = (int)rintf(ny);  iy = min(max(iy, 0), GW - 1);
    int b = t >> 14;
    g_occ[b * NV + (ix << 7) + iy] = 1;
}

__device__ __forceinline__ float coordf(int a, float vsz) {
    return __fadd_rn(-0.3f, __fmul_rn((float)a, vsz));
}

// packed square-fma: {fma(a.x,a.x,c.x), fma(a.y,a.y,c.y)} via FFMA2
__device__ __forceinline__ float2 fma2_sq(float2 a, float2 c) {
    unsigned long long ua, uc, ud;
    memcpy(&ua, &a, 8);
    memcpy(&uc, &c, 8);
    asm("fma.rn.f32x2 %0, %1, %1, %2;" : "=l"(ud) : "l"(ua), "l"(uc));
    float2 d;
    memcpy(&d, &ud, 8);
    return d;
}

__global__ void __launch_bounds__(NTHR, 1) k_fps(
    const float* __restrict__ action,
    const float* __restrict__ cam,
    const float* __restrict__ wv,
    float* __restrict__ out)
{
    __shared__ __align__(16) float colX[GH];  // raw dx per row i
    __shared__ float colY[GW];     // rn(dy*dy) per col j
    __shared__ float redf[NWARP];  // per-warp max d²
    __shared__ int   redi[NWARP];  // per-warp min index in tie window
    __shared__ float s_bias;
    __shared__ int   s_first;

    const int tid  = threadIdx.x;
    const int lane = tid & 31;
    const int wid  = tid >> 5;
    const int b    = blockIdx.x;
    const float vsz = __fdiv_rn(0.6f, 127.0f);
    const float NEG_INF = __int_as_float(0xFF800000);
    const float POS_INF = __int_as_float(0x7F800000);
    const int   BIGIDX  = 0x7FFFFFFF;

    // ---- per-batch bias: M = T_gl @ E; only its sign margin matters --------
    if (tid == 0) {
        const float tg[3] = {1.0f, -1.0f, -1.0f};
        float a0 = action[b * 4 + 0], a1 = action[b * 4 + 1];
        float a2 = action[b * 4 + 2], a3 = action[b * 4 + 3];
        float bias = 0.0f;
        #pragma unroll
        for (int r = 0; r < 3; r++) {
            float m0 = tg[r] * cam[r * 4 + 0];
            float m2 = tg[r] * cam[r * 4 + 2];
            float m3 = tg[r] * cam[r * 4 + 3];
            float s3 = (m0 * a0 + m2 * (-a1) + m3) / 24.0f;
            float e3 = (m0 * a2 + m2 * (-a3) + m3) / 24.0f;
            bias += wv[r] * s3 + wv[3 + r] * e3;
        }
        s_bias  = bias;
        s_first = BIGIDX;
    }
    __syncthreads();
    const float bias = s_bias;
    const bool mOcc = (__fadd_rn(2.0f, bias) >= 0.0f);
    const bool mEmp = (__fsub_rn(bias, 2.0f) >= 0.0f);

    // ---- element mapping: thread owns rows rbase..rbase+31, column jj ------
    const int i0    = tid >> 7;          // 0..3 (warp-uniform)
    const int jj    = tid & 127;         // column
    const int rbase = i0 * 32;           // first row of this thread's chunk
    const int vbase = i0 * 4096 + jj;    // voxel index base (+ k*128)

    // ---- init mask / d² state; first masked voxel --------------------------
    float dsq[EPT];
    int firstM = BIGIDX;
    #pragma unroll
    for (int k = 0; k < EPT; k++) {
        int v = vbase + k * 128;         // ascending in k ✓
        bool m = g_occ[b * NV + v] ? mOcc : mEmp;
        dsq[k] = m ? POS_INF : NEG_INF;
        if (m && firstM == BIGIDX) firstM = v;
    }
    if (firstM != BIGIDX) atomicMin(&s_first, firstM);
    __syncthreads();
    int startv = s_first;
    if (startv == BIGIDX) {
        startv = 0;
        #pragma unroll
        for (int k = 0; k < EPT; k++) dsq[k] = POS_INF;
    }
    if (tid == 0) {
        size_t o3 = (size_t)b * NPART_OUT * 3;
        out[o3 + 0] = coordf(startv >> 7, vsz);
        out[o3 + 1] = coordf(startv & 127, vsz);
        out[o3 + 2] = 0.745f;
    }

    int fpv = startv;

    for (int it = 1; it < NPART_OUT; it++) {
        const int pi = fpv >> 7, pj = fpv & 127;
        // ---- build distance columns ----------------------------------------
        if (tid < GH) {
            colX[tid] = __fsub_rn(coordf(tid, vsz), coordf(pi, vsz));
        } else if (tid < GH + GW) {
            int j = tid - GH;
            float d = __fsub_rn(coordf(j, vsz), coordf(pj, vsz));
            colY[j] = __fmul_rn(d, d);
        }
        __syncthreads();                                   // syncB

        // ---- pass 1: min-update + block max of d² --------------------------
        const float cy = colY[jj];
        float m0 = NEG_INF, m1 = NEG_INF, m2a = NEG_INF, m3 = NEG_INF;
        if (it == 1) {
            // form0 (eager init): rn(rn(dx*dx) + dy²col)
            #pragma unroll
            for (int k = 0; k < EPT; k += 4) {
                float4 c4 = *reinterpret_cast<const float4*>(&colX[rbase + k]);
                float s0 = __fadd_rn(__fmul_rn(c4.x, c4.x), cy);
                float s1 = __fadd_rn(__fmul_rn(c4.y, c4.y), cy);
                float s2 = __fadd_rn(__fmul_rn(c4.z, c4.z), cy);
                float s3 = __fadd_rn(__fmul_rn(c4.w, c4.w), cy);
                dsq[k+0] = fminf(dsq[k+0], s0);  m0 = fmaxf(m0, dsq[k+0]);
                dsq[k+1] = fminf(dsq[k+1], s1);  m1 = fmaxf(m1, dsq[k+1]);
                dsq[k+2] = fminf(dsq[k+2], s2);  m2a = fmaxf(m2a, dsq[k+2]);
                dsq[k+3] = fminf(dsq[k+3], s3);  m3 = fmaxf(m3, dsq[k+3]);
            }
        } else {
            // form2 (scan body): fma(dx,dx, dy²col), packed FFMA2
            const float2 cy2 = make_float2(cy, cy);
            #pragma unroll
            for (int k = 0; k < EPT; k += 4) {
                float4 c4 = *reinterpret_cast<const float4*>(&colX[rbase + k]);
                float2 s01 = fma2_sq(make_float2(c4.x, c4.y), cy2);
                float2 s23 = fma2_sq(make_float2(c4.z, c4.w), cy2);
                dsq[k+0] = fminf(dsq[k+0], s01.x);  m0 = fmaxf(m0, dsq[k+0]);
                dsq[k+1] = fminf(dsq[k+1], s01.y);  m1 = fmaxf(m1, dsq[k+1]);
                dsq[k+2] = fminf(dsq[k+2], s23.x);  m2a = fmaxf(m2a, dsq[k+2]);
                dsq[k+3] = fminf(dsq[k+3], s23.y);  m3 = fmaxf(m3, dsq[k+3]);
            }
        }
        float wmax = fmaxf(fmaxf(m0, m1), fmaxf(m2a, m3));
        #pragma unroll
        for (int o = 16; o > 0; o >>= 1)
            wmax = fmaxf(wmax, __shfl_xor_sync(0xFFFFFFFFu, wmax, o));
        if (lane == 0) redf[wid] = wmax;
        __syncthreads();                                   // syncC

        // ---- block max M2, tie-window lower bound L (all threads) ----------
        float M2 = redf[0];
        #pragma unroll
        for (int w = 1; w < NWARP; w++) M2 = fmaxf(M2, redf[w]);
        float L = M2;
        if (M2 > 0.0f) {
            float S = __fsqrt_rn(M2);
            unsigned u = __float_as_uint(M2);
            #pragma unroll 1
            while (u > 0u && __fsqrt_rn(__uint_as_float(u - 1u)) == S) u--;
            L = __uint_as_float(u);
        }

        // ---- pass 2: first index with d² >= L; only candidate warps scan ---
        int wmin = BIGIDX;
        if (wmax >= L) {                 // warp-uniform branch
            int b0 = BIGIDX, b1 = BIGIDX, b2 = BIGIDX, b3 = BIGIDX;
            #pragma unroll
            for (int k = 0; k < EPT; k += 4) {
                b0 = min(b0, (dsq[k+0] >= L) ? (vbase + (k+0) * 128) : BIGIDX);
                b1 = min(b1, (dsq[k+1] >= L) ? (vbase + (k+1) * 128) : BIGIDX);
                b2 = min(b2, (dsq[k+2] >= L) ? (vbase + (k+2) * 128) : BIGIDX);
                b3 = min(b3, (dsq[k+3] >= L) ? (vbase + (k+3) * 128) : BIGIDX);
            }
            wmin = min(min(b0, b1), min(b2, b3));
            #pragma unroll
            for (int o = 16; o > 0; o >>= 1)
                wmin = min(wmin, __shfl_xor_sync(0xFFFFFFFFu, wmin, o));
        }
        if (lane == 0) redi[wid] = wmin;
        __syncthreads();                                   // syncE

        int v = redi[0];
        #pragma unroll
        for (int w = 1; w < NWARP; w++) v = min(v, redi[w]);
        fpv = v;
        if (tid == 0) {
            size_t o3 = ((size_t)b * NPART_OUT + it) * 3;
            out[o3 + 0] = coordf(v >> 7, vsz);
            out[o3 + 1] = coordf(v & 127, vsz);
            out[o3 + 2] = 0.745f;
        }
    }
}

// ---------------------------------------------------------------------------
// Inputs bound BY ELEMENT COUNT (all five sizes distinct):
//   s_cur 6291456 | action 512 | cam 16 | w_action 6 | n_particles 1 (unused)
// Output: f32 (128, 512, 3)
// ---------------------------------------------------------------------------
extern "C" void kernel_launch(void* const* d_in, const int* in_sizes, int n_in,
                              void* d_out, int out_size) {
    const float* s_cur  = nullptr;
    const float* action = nullptr;
    const float* cam    = nullptr;
    const float* wv     = nullptr;
    for (int i = 0; i < n_in; i++) {
        switch (in_sizes[i]) {
            case NB * NPTS * 3: s_cur  = (const float*)d_in[i]; break;
            case NB * 4:        action = (const float*)d_in[i]; break;
            case 16:            cam    = (const float*)d_in[i]; break;
            case 6:             wv     = (const float*)d_in[i]; break;
            default: break;
        }
    }
    if (!s_cur)  s_cur  = (const float*)d_in[0];
    if (!action) action = (const float*)d_in[1];
    if (!cam)    cam    = (const float*)d_in[2];
    if (!wv)     wv     = (const float*)d_in[3];
    float* out = (float*)d_out;

    k_zero<<<(NB * NV / 16) / 256, 256>>>();
    k_scatter<<<(NB * NPTS) / 256, 256>>>(s_cur);
    k_fps<<<NB, NTHR>>>(action, cam, wv, out);
}

// round 11
// speedup vs baseline: 5.6382x; 1.3674x over previous
#include <cuda_runtime.h>
#include <cstdint>
#include <cstring>

#define NB 128
#define NPTS 16384
#define GH 128
#define GW 128
#define NV (GH*GW)
#define NPART_OUT 512
#define NTHR 512
#define EPT (NV/NTHR)   // 32 elements per thread
#define NWARP (NTHR/32)

// Reference execution model (eager JAX + compiled lax.scan) — bitwise:
//   coords:      c(i) = rn(-0.3 + rn(i*vsz))          (eager, no fma)
//   init dist²:  rn(rn(dx*dx) + rn(dy*dy))            (eager, form0)
//   scan dist²:  fma(dx, dx, rn(dy*dy))               (fused scan body, form2)
//   d = sqrt.rn(d²); argmax in sqrt domain, first-index tie-break.
// Sqrt-free argmax: preimage of S=sqrt_rn(M2) under monotone sqrt_rn is an
// interval [L, M2]; first index with d² >= L == reference argmax. Exact.
// Warp-tile skip: sv_min (nearest row/col) >= warp max  =>  update is a no-op.

__device__ unsigned char g_occ[NB * NV];

__global__ void k_zero() {
    int i = blockIdx.x * blockDim.x + threadIdx.x;
    reinterpret_cast<uint4*>(g_occ)[i] = make_uint4(0u, 0u, 0u, 0u);
}

__global__ void k_scatter(const float* __restrict__ s) {
    int t = blockIdx.x * blockDim.x + threadIdx.x;
    if (t >= NB * NPTS) return;
    float x = s[3 * t + 0];
    float y = s[3 * t + 1];
    float nx = __fmul_rn(__fdiv_rn(__fsub_rn(x, -0.3f), 0.6f), 127.0f);
    float ny = __fmul_rn(__fdiv_rn(__fsub_rn(y, -0.3f), 0.6f), 127.0f);
    int ix = (int)rintf(nx);  ix = min(max(ix, 0), GH - 1);
    int iy = (int)rintf(ny);  iy = min(max(iy, 0), GW - 1);
    int b = t >> 14;
    g_occ[b * NV + (ix << 7) + iy] = 1;
}

__device__ __forceinline__ float coordf(int a, float vsz) {
    return __fadd_rn(-0.3f, __fmul_rn((float)a, vsz));
}

// packed square-fma: {fma(a.x,a.x,c.x), fma(a.y,a.y,c.y)} via FFMA2
__device__ __forceinline__ float2 fma2_sq(float2 a, float2 c) {
    unsigned long long ua, uc, ud;
    memcpy(&ua, &a, 8);
    memcpy(&uc, &c, 8);
    asm("fma.rn.f32x2 %0, %1, %1, %2;" : "=l"(ud) : "l"(ua), "l"(uc));
    float2 d;
    memcpy(&d, &ud, 8);
    return d;
}

__device__ __forceinline__ unsigned redux_max_u32(unsigned v) {
    unsigned d;
    asm("redux.sync.max.u32 %0, %1, 0xffffffff;" : "=r"(d) : "r"(v));
    return d;
}
__device__ __forceinline__ unsigned redux_min_u32(unsigned v) {
    unsigned d;
    asm("redux.sync.min.u32 %0, %1, 0xffffffff;" : "=r"(d) : "r"(v));
    return d;
}
// order-preserving float <-> u32 (no NaNs present)
__device__ __forceinline__ unsigned f2ord(float x) {
    unsigned u = __float_as_uint(x);
    return (u & 0x80000000u) ? ~u : (u | 0x80000000u);
}
__device__ __forceinline__ float ord2f(unsigned o) {
    unsigned u = (o & 0x80000000u) ? (o ^ 0x80000000u) : ~o;
    return __uint_as_float(u);
}

__global__ void __launch_bounds__(NTHR, 1) k_fps(
    const float* __restrict__ action,
    const float* __restrict__ cam,
    const float* __restrict__ wv,
    float* __restrict__ out)
{
    __shared__ __align__(16) float colX[GH];  // raw dx per row i
    __shared__ float colY[GW];       // rn(dy*dy) per col j
    __shared__ unsigned redfu[NWARP];// per-warp max d² (orderable u32)
    __shared__ int   redi[NWARP];    // per-warp min index in tie window
    __shared__ float s_bias;
    __shared__ int   s_first;

    const int tid  = threadIdx.x;
    const int lane = tid & 31;
    const int wid  = tid >> 5;
    const int b    = blockIdx.x;
    const float vsz = __fdiv_rn(0.6f, 127.0f);
    const float NEG_INF = __int_as_float(0xFF800000);
    const float POS_INF = __int_as_float(0x7F800000);
    const int   BIGIDX  = 0x7FFFFFFF;

    // ---- per-batch bias: M = T_gl @ E; only its sign margin matters --------
    if (tid == 0) {
        const float tg[3] = {1.0f, -1.0f, -1.0f};
        float a0 = action[b * 4 + 0], a1 = action[b * 4 + 1];
        float a2 = action[b * 4 + 2], a3 = action[b * 4 + 3];
        float bias = 0.0f;
        #pragma unroll
        for (int r = 0; r < 3; r++) {
            float m0 = tg[r] * cam[r * 4 + 0];
            float m2 = tg[r] * cam[r * 4 + 2];
            float m3 = tg[r] * cam[r * 4 + 3];
            float s3 = (m0 * a0 + m2 * (-a1) + m3) / 24.0f;
            float e3 = (m0 * a2 + m2 * (-a3) + m3) / 24.0f;
            bias += wv[r] * s3 + wv[3 + r] * e3;
        }
        s_bias  = bias;
        s_first = BIGIDX;
    }
    __syncthreads();
    const float bias = s_bias;
    const bool mOcc = (__fadd_rn(2.0f, bias) >= 0.0f);
    const bool mEmp = (__fsub_rn(bias, 2.0f) >= 0.0f);

    // ---- element mapping: warp owns a 32x32 tile ----------------------------
    const int i0    = tid >> 7;          // 0..3 (warp-uniform)
    const int jj    = tid & 127;         // this thread's column
    const int rbase = i0 * 32;           // warp rows  [rbase, rbase+31]
    const int jbase = (wid & 3) * 32;    // warp cols  [jbase, jbase+31]
    const int vbase = i0 * 4096 + jj;    // voxel index base (+ k*128)

    // ---- init mask / d² state; first masked voxel ---------------------------
    float dsq[EPT];
    int firstM = BIGIDX;
    #pragma unroll
    for (int k = 0; k < EPT; k++) {
        int v = vbase + k * 128;
        bool m = g_occ[b * NV + v] ? mOcc : mEmp;
        dsq[k] = m ? POS_INF : NEG_INF;
        if (m && firstM == BIGIDX) firstM = v;
    }
    if (firstM != BIGIDX) atomicMin(&s_first, firstM);
    __syncthreads();
    int startv = s_first;
    if (startv == BIGIDX) {
        startv = 0;
        #pragma unroll
        for (int k = 0; k < EPT; k++) dsq[k] = POS_INF;
    }
    if (tid == 0) {
        size_t o3 = (size_t)b * NPART_OUT * 3;
        out[o3 + 0] = coordf(startv >> 7, vsz);
        out[o3 + 1] = coordf(startv & 127, vsz);
        out[o3 + 2] = 0.745f;
    }

    int fpv = startv;
    float m_w = NEG_INF;   // warp max of dsq (uniform), valid from it==1 on

    for (int it = 1; it < NPART_OUT; it++) {
        const int pi = fpv >> 7, pj = fpv & 127;
        // ---- build distance columns -----------------------------------------
        if (tid < GH) {
            colX[tid] = __fsub_rn(coordf(tid, vsz), coordf(pi, vsz));
        } else if (tid < GH + GW) {
            int j = tid - GH;
            float d = __fsub_rn(coordf(j, vsz), coordf(pj, vsz));
            colY[j] = __fmul_rn(d, d);
        }
        __syncthreads();                                   // syncB

        // ---- pass 1: min-update + warp max of d² ----------------------------
        const float cy = colY[jj];
        if (it == 1) {
            // form0 (eager init): rn(rn(dx*dx) + dy²col) — always full update
            float m0 = NEG_INF, m1 = NEG_INF, m2a = NEG_INF, m3 = NEG_INF;
            #pragma unroll
            for (int k = 0; k < EPT; k += 4) {
                float4 c4 = *reinterpret_cast<const float4*>(&colX[rbase + k]);
                float s0 = __fadd_rn(__fmul_rn(c4.x, c4.x), cy);
                float s1 = __fadd_rn(__fmul_rn(c4.y, c4.y), cy);
                float s2 = __fadd_rn(__fmul_rn(c4.z, c4.z), cy);
                float s3 = __fadd_rn(__fmul_rn(c4.w, c4.w), cy);
                dsq[k+0] = fminf(dsq[k+0], s0);  m0 = fmaxf(m0, dsq[k+0]);
                dsq[k+1] = fminf(dsq[k+1], s1);  m1 = fmaxf(m1, dsq[k+1]);
                dsq[k+2] = fminf(dsq[k+2], s2);  m2a = fmaxf(m2a, dsq[k+2]);
                dsq[k+3] = fminf(dsq[k+3], s3);  m3 = fmaxf(m3, dsq[k+3]);
            }
            float wm = fmaxf(fmaxf(m0, m1), fmaxf(m2a, m3));
            m_w = ord2f(redux_max_u32(f2ord(wm)));
        } else {
            // warp-tile skip test: minimal candidate over the 32x32 tile
            int rn_ = min(max(pi, rbase), rbase + 31);
            int jn_ = min(max(pj, jbase), jbase + 31);
            float dxn = colX[rn_];
            float cyn = colY[jn_];
            float svmin = __fmaf_rn(dxn, dxn, cyn);
            if (svmin < m_w) {           // warp-uniform branch
                const float2 cy2 = make_float2(cy, cy);
                float m0 = NEG_INF, m1 = NEG_INF, m2a = NEG_INF, m3 = NEG_INF;
                #pragma unroll
                for (int k = 0; k < EPT; k += 4) {
                    float4 c4 = *reinterpret_cast<const float4*>(&colX[rbase + k]);
                    float2 s01 = fma2_sq(make_float2(c4.x, c4.y), cy2);
                    float2 s23 = fma2_sq(make_float2(c4.z, c4.w), cy2);
                    dsq[k+0] = fminf(dsq[k+0], s01.x);  m0 = fmaxf(m0, dsq[k+0]);
                    dsq[k+1] = fminf(dsq[k+1], s01.y);  m1 = fmaxf(m1, dsq[k+1]);
                    dsq[k+2] = fminf(dsq[k+2], s23.x);  m2a = fmaxf(m2a, dsq[k+2]);
                    dsq[k+3] = fminf(dsq[k+3], s23.y);  m3 = fmaxf(m3, dsq[k+3]);
                }
                float wm = fmaxf(fmaxf(m0, m1), fmaxf(m2a, m3));
                m_w = ord2f(redux_max_u32(f2ord(wm)));
            }
            // else: bitwise no-op for every element; m_w unchanged
        }
        if (lane == 0) redfu[wid] = f2ord(m_w);
        __syncthreads();                                   // syncC

        // ---- block max M2, tie-window lower bound L (all threads) -----------
        unsigned Mu = redfu[0];
        #pragma unroll
        for (int w = 1; w < NWARP; w++) Mu = max(Mu, redfu[w]);
        float M2 = ord2f(Mu);
        float L = M2;
        if (M2 > 0.0f) {
            float S = __fsqrt_rn(M2);
            unsigned u = __float_as_uint(M2);
            #pragma unroll 1
            while (u > 0u && __fsqrt_rn(__uint_as_float(u - 1u)) == S) u--;
            L = __uint_as_float(u);
        }

        // ---- pass 2: first index with d² >= L; only candidate warps scan ----
        int wmin = BIGIDX;
        if (m_w >= L) {                  // warp-uniform branch
            int b0 = BIGIDX, b1 = BIGIDX, b2 = BIGIDX, b3 = BIGIDX;
            #pragma unroll
            for (int k = 0; k < EPT; k += 4) {
                b0 = min(b0, (dsq[k+0] >= L) ? (vbase + (k+0) * 128) : BIGIDX);
                b1 = min(b1, (dsq[k+1] >= L) ? (vbase + (k+1) * 128) : BIGIDX);
                b2 = min(b2, (dsq[k+2] >= L) ? (vbase + (k+2) * 128) : BIGIDX);
                b3 = min(b3, (dsq[k+3] >= L) ? (vbase + (k+3) * 128) : BIGIDX);
            }
            wmin = (int)redux_min_u32((unsigned)min(min(b0, b1), min(b2, b3)));
        }
        if (lane == 0) redi[wid] = wmin;
        __syncthreads();                                   // syncE

        int v = redi[0];
        #pragma unroll
        for (int w = 1; w < NWARP; w++) v = min(v, redi[w]);
        fpv = v;
        if (tid == 0) {
            size_t o3 = ((size_t)b * NPART_OUT + it) * 3;
            out[o3 + 0] = coordf(v >> 7, vsz);
            out[o3 + 1] = coordf(v & 127, vsz);
            out[o3 + 2] = 0.745f;
        }
    }
}

// ---------------------------------------------------------------------------
// Inputs bound BY ELEMENT COUNT (all five sizes distinct):
//   s_cur 6291456 | action 512 | cam 16 | w_action 6 | n_particles 1 (unused)
// Output: f32 (128, 512, 3)
// ---------------------------------------------------------------------------
extern "C" void kernel_launch(void* const* d_in, const int* in_sizes, int n_in,
                              void* d_out, int out_size) {
    const float* s_cur  = nullptr;
    const float* action = nullptr;
    const float* cam    = nullptr;
    const float* wv     = nullptr;
    for (int i = 0; i < n_in; i++) {
        switch (in_sizes[i]) {
            case NB * NPTS * 3: s_cur  = (const float*)d_in[i]; break;
            case NB * 4:        action = (const float*)d_in[i]; break;
            case 16:            cam    = (const float*)d_in[i]; break;
            case 6:             wv     = (const float*)d_in[i]; break;
            default: break;
        }
    }
    if (!s_cur)  s_cur  = (const float*)d_in[0];
    if (!action) action = (const float*)d_in[1];
    if (!cam)    cam    = (const float*)d_in[2];
    if (!wv)     wv     = (const float*)d_in[3];
    float* out = (float*)d_out;

    k_zero<<<(NB * NV / 16) / 256, 256>>>();
    k_scatter<<<(NB * NPTS) / 256, 256>>>(s_cur);
    k_fps<<<NB, NTHR>>>(action, cam, wv, out);
}

// round 12
// speedup vs baseline: 7.2397x; 1.2840x over previous
#include <cuda_runtime.h>
#include <cstdint>
#include <cstring>

#define NB 128
#define NPTS 16384
#define GH 128
#define GW 128
#define NV (GH*GW)
#define NPART_OUT 512
#define NTHR 512
#define EPT (NV/NTHR)   // 32 elements per thread
#define NWARP (NTHR/32)

// Reference execution model (eager JAX + compiled lax.scan) — bitwise:
//   coords:      c(i) = rn(-0.3 + rn(i*vsz))          (eager, no fma)
//   init dist²:  rn(rn(dx*dx) + rn(dy*dy))            (eager, form0)
//   scan dist²:  fma(dx, dx, rn(dy*dy))               (fused scan body, form2)
//   d = sqrt.rn(d²); argmax in sqrt domain, first-index tie-break.
// Sqrt-free argmax: preimage of S=sqrt_rn(M2) under monotone sqrt_rn is an
// interval [L, M2]; first index with d² >= L == reference argmax. Exact.
// Warp-tile skip: minimal candidate over the warp's 32x32 tile >= warp max
// => every fminf is a bitwise no-op => skip the whole update loop. Exact.

__device__ unsigned char g_occ[NB * NV];

__global__ void k_zero() {
    int i = blockIdx.x * blockDim.x + threadIdx.x;
    reinterpret_cast<uint4*>(g_occ)[i] = make_uint4(0u, 0u, 0u, 0u);
}

__global__ void k_scatter(const float* __restrict__ s) {
    int t = blockIdx.x * blockDim.x + threadIdx.x;
    if (t >= NB * NPTS) return;
    float x = s[3 * t + 0];
    float y = s[3 * t + 1];
    float nx = __fmul_rn(__fdiv_rn(__fsub_rn(x, -0.3f), 0.6f), 127.0f);
    float ny = __fmul_rn(__fdiv_rn(__fsub_rn(y, -0.3f), 0.6f), 127.0f);
    int ix = (int)rintf(nx);  ix = min(max(ix, 0), GH - 1);
    int iy = (int)rintf(ny);  iy = min(max(iy, 0), GW - 1);
    int b = t >> 14;
    g_occ[b * NV + (ix << 7) + iy] = 1;
}

__device__ __forceinline__ float coordf(int a, float vsz) {
    return __fadd_rn(-0.3f, __fmul_rn((float)a, vsz));
}

__device__ __forceinline__ unsigned redux_max_u32(unsigned v) {
    unsigned d;
    asm("redux.sync.max.u32 %0, %1, 0xffffffff;" : "=r"(d) : "r"(v));
    return d;
}
__device__ __forceinline__ unsigned redux_min_u32(unsigned v) {
    unsigned d;
    asm("redux.sync.min.u32 %0, %1, 0xffffffff;" : "=r"(d) : "r"(v));
    return d;
}
// order-preserving float <-> u32 (no NaNs present)
__device__ __forceinline__ unsigned f2ord(float x) {
    unsigned u = __float_as_uint(x);
    return (u & 0x80000000u) ? ~u : (u | 0x80000000u);
}
__device__ __forceinline__ float ord2f(unsigned o) {
    unsigned u = (o & 0x80000000u) ? (o ^ 0x80000000u) : ~o;
    return __uint_as_float(u);
}

__global__ void __launch_bounds__(NTHR, 1) k_fps(
    const float* __restrict__ action,
    const float* __restrict__ cam,
    const float* __restrict__ wv,
    float* __restrict__ out)
{
    __shared__ unsigned redfu[NWARP];  // per-warp max d² (orderable u32)
    __shared__ int      redi[NWARP];   // per-warp min index in tie window
    __shared__ float    s_bias;
    __shared__ int      s_first;

    const int tid  = threadIdx.x;
    const int lane = tid & 31;
    const int wid  = tid >> 5;
    const int b    = blockIdx.x;
    const float vsz = __fdiv_rn(0.6f, 127.0f);
    const float NEG_INF = __int_as_float(0xFF800000);
    const float POS_INF = __int_as_float(0x7F800000);
    const int   BIGIDX  = 0x7FFFFFFF;

    // ---- per-batch bias: M = T_gl @ E; only its sign margin matters --------
    if (tid == 0) {
        const float tg[3] = {1.0f, -1.0f, -1.0f};
        float a0 = action[b * 4 + 0], a1 = action[b * 4 + 1];
        float a2 = action[b * 4 + 2], a3 = action[b * 4 + 3];
        float bias = 0.0f;
        #pragma unroll
        for (int r = 0; r < 3; r++) {
            float m0 = tg[r] * cam[r * 4 + 0];
            float m2 = tg[r] * cam[r * 4 + 2];
            float m3 = tg[r] * cam[r * 4 + 3];
            float s3 = (m0 * a0 + m2 * (-a1) + m3) / 24.0f;
            float e3 = (m0 * a2 + m2 * (-a3) + m3) / 24.0f;
            bias += wv[r] * s3 + wv[3 + r] * e3;
        }
        s_bias  = bias;
        s_first = BIGIDX;
    }
    __syncthreads();
    const float bias = s_bias;
    const bool mOcc = (__fadd_rn(2.0f, bias) >= 0.0f);
    const bool mEmp = (__fsub_rn(bias, 2.0f) >= 0.0f);

    // ---- element mapping: warp owns a 32x32 tile ----------------------------
    const int i0    = tid >> 7;          // 0..3 (warp-uniform)
    const int jj    = tid & 127;         // this thread's column
    const int rbase = i0 * 32;           // warp rows  [rbase, rbase+31]
    const int jbase = (wid & 3) * 32;    // warp cols  [jbase, jbase+31]
    const int vbase = i0 * 4096 + jj;    // voxel index base (+ k*128)

    // iteration-invariant coordinates in registers
    float cr[EPT];                       // row coords for this thread's rows
    #pragma unroll
    for (int k = 0; k < EPT; k++) cr[k] = coordf(rbase + k, vsz);
    const float cj = coordf(jj, vsz);    // this thread's column coord

    // ---- init mask / d² state; first masked voxel ---------------------------
    float dsq[EPT];
    int firstM = BIGIDX;
    #pragma unroll
    for (int k = 0; k < EPT; k++) {
        int v = vbase + k * 128;
        bool m = g_occ[b * NV + v] ? mOcc : mEmp;
        dsq[k] = m ? POS_INF : NEG_INF;
        if (m && firstM == BIGIDX) firstM = v;
    }
    if (firstM != BIGIDX) atomicMin(&s_first, firstM);
    __syncthreads();
    int startv = s_first;
    if (startv == BIGIDX) {
        startv = 0;
        #pragma unroll
        for (int k = 0; k < EPT; k++) dsq[k] = POS_INF;
    }
    if (tid == 0) {
        size_t o3 = (size_t)b * NPART_OUT * 3;
        out[o3 + 0] = coordf(startv >> 7, vsz);
        out[o3 + 1] = coordf(startv & 127, vsz);
        out[o3 + 2] = 0.745f;
    }

    int fpv = startv;
    float m_w = NEG_INF;   // warp max of dsq (uniform), valid from it==1 on

    for (int it = 1; it < NPART_OUT; it++) {
        const int pi = fpv >> 7, pj = fpv & 127;
        const float cpi = coordf(pi, vsz);
        const float cpj = coordf(pj, vsz);
        const float dyj = __fsub_rn(cj, cpj);
        const float cy  = __fmul_rn(dyj, dyj);     // rn(dy²), this thread's col

        // ---- pass 1: min-update + warp max of d² (register-only math) -------
        if (it == 1) {
            // form0 (eager init): rn(rn(dx*dx) + cy) — always full update
            float m0 = NEG_INF, m1 = NEG_INF, m2a = NEG_INF, m3 = NEG_INF;
            #pragma unroll
            for (int k = 0; k < EPT; k += 4) {
                float d0 = __fsub_rn(cr[k+0], cpi);
                float d1 = __fsub_rn(cr[k+1], cpi);
                float d2 = __fsub_rn(cr[k+2], cpi);
                float d3 = __fsub_rn(cr[k+3], cpi);
                float s0 = __fadd_rn(__fmul_rn(d0, d0), cy);
                float s1 = __fadd_rn(__fmul_rn(d1, d1), cy);
                float s2 = __fadd_rn(__fmul_rn(d2, d2), cy);
                float s3 = __fadd_rn(__fmul_rn(d3, d3), cy);
                dsq[k+0] = fminf(dsq[k+0], s0);  m0 = fmaxf(m0, dsq[k+0]);
                dsq[k+1] = fminf(dsq[k+1], s1);  m1 = fmaxf(m1, dsq[k+1]);
                dsq[k+2] = fminf(dsq[k+2], s2);  m2a = fmaxf(m2a, dsq[k+2]);
                dsq[k+3] = fminf(dsq[k+3], s3);  m3 = fmaxf(m3, dsq[k+3]);
            }
            float wm = fmaxf(fmaxf(m0, m1), fmaxf(m2a, m3));
            m_w = ord2f(redux_max_u32(f2ord(wm)));
        } else {
            // warp-tile skip: minimal candidate over the 32x32 tile (uniform)
            int rn_ = min(max(pi, rbase), rbase + 31);
            int jn_ = min(max(pj, jbase), jbase + 31);
            float dxn = __fsub_rn(coordf(rn_, vsz), cpi);
            float dyn = __fsub_rn(coordf(jn_, vsz), cpj);
            float svmin = __fmaf_rn(dxn, dxn, __fmul_rn(dyn, dyn));
            if (svmin < m_w) {           // warp-uniform branch
                float m0 = NEG_INF, m1 = NEG_INF, m2a = NEG_INF, m3 = NEG_INF;
                #pragma unroll
                for (int k = 0; k < EPT; k += 4) {
                    float d0 = __fsub_rn(cr[k+0], cpi);
                    float d1 = __fsub_rn(cr[k+1], cpi);
                    float d2 = __fsub_rn(cr[k+2], cpi);
                    float d3 = __fsub_rn(cr[k+3], cpi);
                    float s0 = __fmaf_rn(d0, d0, cy);   // form2: fma(dx,dx,cy)
                    float s1 = __fmaf_rn(d1, d1, cy);
                    float s2 = __fmaf_rn(d2, d2, cy);
                    float s3 = __fmaf_rn(d3, d3, cy);
                    dsq[k+0] = fminf(dsq[k+0], s0);  m0 = fmaxf(m0, dsq[k+0]);
                    dsq[k+1] = fminf(dsq[k+1], s1);  m1 = fmaxf(m1, dsq[k+1]);
                    dsq[k+2] = fminf(dsq[k+2], s2);  m2a = fmaxf(m2a, dsq[k+2]);
                    dsq[k+3] = fminf(dsq[k+3], s3);  m3 = fmaxf(m3, dsq[k+3]);
                }
                float wm = fmaxf(fmaxf(m0, m1), fmaxf(m2a, m3));
                m_w = ord2f(redux_max_u32(f2ord(wm)));
            }
        }
        if (lane == 0) redfu[wid] = f2ord(m_w);
        __syncthreads();                                   // syncC

        // ---- block max via lane-indexed LDS + redux -------------------------
        unsigned Mu = redux_max_u32(redfu[lane & (NWARP - 1)]);
        float M2 = ord2f(Mu);
        float L = M2;
        if (M2 > 0.0f) {
            float S = __fsqrt_rn(M2);
            unsigned u = __float_as_uint(M2);
            #pragma unroll 1
            while (u > 0u && __fsqrt_rn(__uint_as_float(u - 1u)) == S) u--;
            L = __uint_as_float(u);
        }

        // ---- pass 2: first index with d² >= L; only candidate warps scan ----
        int wmin = BIGIDX;
        if (m_w >= L) {                  // warp-uniform branch
            int b0 = BIGIDX, b1 = BIGIDX, b2 = BIGIDX, b3 = BIGIDX;
            #pragma unroll
            for (int k = 0; k < EPT; k += 4) {
                b0 = min(b0, (dsq[k+0] >= L) ? (vbase + (k+0) * 128) : BIGIDX);
                b1 = min(b1, (dsq[k+1] >= L) ? (vbase + (k+1) * 128) : BIGIDX);
                b2 = min(b2, (dsq[k+2] >= L) ? (vbase + (k+2) * 128) : BIGIDX);
                b3 = min(b3, (dsq[k+3] >= L) ? (vbase + (k+3) * 128) : BIGIDX);
            }
            wmin = (int)redux_min_u32((unsigned)min(min(b0, b1), min(b2, b3)));
        }
        if (lane == 0) redi[wid] = wmin;
        __syncthreads();                                   // syncE

        int v = (int)redux_min_u32((unsigned)redi[lane & (NWARP - 1)]);
        fpv = v;
        if (tid == 0) {
            size_t o3 = ((size_t)b * NPART_OUT + it) * 3;
            out[o3 + 0] = coordf(v >> 7, vsz);
            out[o3 + 1] = coordf(v & 127, vsz);
            out[o3 + 2] = 0.745f;
        }
    }
}

// ---------------------------------------------------------------------------
// Inputs bound BY ELEMENT COUNT (all five sizes distinct):
//   s_cur 6291456 | action 512 | cam 16 | w_action 6 | n_particles 1 (unused)
// Output: f32 (128, 512, 3)
// ---------------------------------------------------------------------------
extern "C" void kernel_launch(void* const* d_in, const int* in_sizes, int n_in,
                              void* d_out, int out_size) {
    const float* s_cur  = nullptr;
    const float* action = nullptr;
    const float* cam    = nullptr;
    const float* wv     = nullptr;
    for (int i = 0; i < n_in; i++) {
        switch (in_sizes[i]) {
            case NB * NPTS * 3: s_cur  = (const float*)d_in[i]; break;
            case NB * 4:        action = (const float*)d_in[i]; break;
            case 16:            cam    = (const float*)d_in[i]; break;
            case 6:             wv     = (const float*)d_in[i]; break;
            default: break;
        }
    }
    if (!s_cur)  s_cur  = (const float*)d_in[0];
    if (!action) action = (const float*)d_in[1];
    if (!cam)    cam    = (const float*)d_in[2];
    if (!wv)     wv     = (const float*)d_in[3];
    float* out = (float*)d_out;

    k_zero<<<(NB * NV / 16) / 256, 256>>>();
    k_scatter<<<(NB * NPTS) / 256, 256>>>(s_cur);
    k_fps<<<NB, NTHR>>>(action, cam, wv, out);
}